// round 16
// baseline (speedup 1.0000x reference)
#include <cuda_runtime.h>
#include <cuda_fp16.h>
#include <math.h>

#define SEQ 4096
#define DM 1024
#define NH 16
#define DKH 64
#define SC2 0.18033688011112042f   // 0.125 * log2(e)
#define ONESH2 0x3C003C00u         // half2(1.0, 1.0)

// ---------------- scratch ----------------
__device__ __half g_xh[SEQ * DM];
__device__ __half g_wqkvh[3 * DM * DM];
__device__ __half g_woh[DM * DM];
__device__ __half g_qh[NH * SEQ * DKH];
__device__ __half g_kh[NH * SEQ * DKH];
__device__ __half g_vh[NH * SEQ * DKH];
__device__ __half g_attnh[SEQ * DM];

// ---------------- helpers ----------------
__device__ __forceinline__ float ex2f(float x) {
    float y;
    asm("ex2.approx.ftz.f32 %0, %1;" : "=f"(y) : "f"(x));
    return y;
}
__device__ __forceinline__ unsigned h2ex2(unsigned x) {
    unsigned y;
    asm("ex2.approx.f16x2 %0, %1;" : "=r"(y) : "r"(x));
    return y;
}
__device__ __forceinline__ void mma16h(float* d, unsigned a0, unsigned a1,
                                       unsigned a2, unsigned a3,
                                       unsigned b0, unsigned b1) {
    asm volatile(
        "mma.sync.aligned.m16n8k16.row.col.f32.f16.f16.f32 "
        "{%0,%1,%2,%3},{%4,%5,%6,%7},{%8,%9},{%0,%1,%2,%3};"
        : "+f"(d[0]), "+f"(d[1]), "+f"(d[2]), "+f"(d[3])
        : "r"(a0), "r"(a1), "r"(a2), "r"(a3), "r"(b0), "r"(b1));
}
__device__ __forceinline__ unsigned pack_h2(float x, float y) {
    __half2 h = __floats2half2_rn(x, y);
    return *(unsigned*)&h;
}
__device__ __forceinline__ unsigned smem_u32(const void* p) {
    unsigned a;
    asm("{ .reg .u64 t; cvta.to.shared.u64 t, %1; cvt.u32.u64 %0, t; }"
        : "=r"(a) : "l"(p));
    return a;
}
__device__ __forceinline__ void cpa16(unsigned s, const void* g) {
    asm volatile("cp.async.cg.shared.global [%0], [%1], 16;" :: "r"(s), "l"(g));
}
#define LDSM4(r0,r1,r2,r3,addr) \
    asm volatile("ldmatrix.sync.aligned.m8n8.x4.shared.b16 {%0,%1,%2,%3},[%4];" \
        : "=r"(r0),"=r"(r1),"=r"(r2),"=r"(r3) : "r"(addr))
#define LDSM4T(r0,r1,r2,r3,addr) \
    asm volatile("ldmatrix.sync.aligned.m8n8.x4.trans.shared.b16 {%0,%1,%2,%3},[%4];" \
        : "=r"(r0),"=r"(r1),"=r"(r2),"=r"(r3) : "r"(addr))

// ---------------- fused f32 -> f16 convert ----------------
__global__ void f2h_all(const float* __restrict__ x, const float* __restrict__ wqkv,
                        const float* __restrict__ wo, __half* __restrict__ xh,
                        __half* __restrict__ wqkvh, __half* __restrict__ woh)
{
    int i = blockIdx.x * blockDim.x + threadIdx.x;
    const int NX = SEQ * DM / 4;
    const int NW = 3 * DM * DM / 4;
    const float* src; __half* dst; int j;
    if (i < NX)            { src = x;    dst = xh;    j = i; }
    else if (i < NX + NW)  { src = wqkv; dst = wqkvh; j = i - NX; }
    else                   { src = wo;   dst = woh;   j = i - NX - NW; }
    float4 v = ((const float4*)src)[j];
    ((__half2*)dst)[2 * j]     = __floats2half2_rn(v.x, v.y);
    ((__half2*)dst)[2 * j + 1] = __floats2half2_rn(v.z, v.w);
}

// ======== shared GEMM mainloop (128x128, BK=64, double-buffered) ===========
// Variadic: epilogue blocks may contain top-level commas.
#define GEMM_BODY(...)                                                         \
    __shared__ __half As[2][8192];                                             \
    __shared__ __half Bs[2][8192];                                             \
    unsigned Ab = smem_u32(As);                                                \
    unsigned Bb = smem_u32(Bs);                                                \
    int tid = threadIdx.x;                                                     \
    int lane = tid & 31, w = tid >> 5;                                         \
    int wm = w >> 2, wn = w & 3;                                               \
    int m0 = blockIdx.y * 128, n0 = blockIdx.x * 128;                          \
    float acc[4][4][4];                                                        \
    _Pragma("unroll")                                                          \
    for (int a = 0; a < 4; a++)                                                \
        _Pragma("unroll")                                                      \
        for (int b = 0; b < 4; b++)                                            \
            _Pragma("unroll")                                                  \
            for (int c = 0; c < 4; c++) acc[a][b][c] = 0.0f;                   \
    int nk = K / 64;                                                           \
    _Pragma("unroll")                                                          \
    for (int it = 0; it < 4; it++) {                                           \
        int f = tid + it * 256;                                                \
        int r = f >> 3, c = f & 7;                                             \
        unsigned soff = r * 128 + ((c ^ (r & 7)) << 4);                        \
        cpa16(Ab + soff, A + (size_t)(m0 + r) * K + c * 8);                    \
        cpa16(Bb + soff, B + (size_t)(n0 + r) * K + c * 8);                    \
    }                                                                          \
    asm volatile("cp.async.commit_group;");                                    \
    for (int kc = 0; kc < nk; kc++) {                                          \
        int st = kc & 1;                                                       \
        __syncthreads();                                                       \
        if (kc + 1 < nk) {                                                     \
            unsigned sb = (st ^ 1) * 16384;                                    \
            int kg = (kc + 1) * 64;                                            \
            _Pragma("unroll")                                                  \
            for (int it = 0; it < 4; it++) {                                   \
                int f = tid + it * 256;                                        \
                int r = f >> 3, c = f & 7;                                     \
                unsigned soff = sb + r * 128 + ((c ^ (r & 7)) << 4);           \
                cpa16(Ab + soff, A + (size_t)(m0 + r) * K + kg + c * 8);       \
                cpa16(Bb + soff, B + (size_t)(n0 + r) * K + kg + c * 8);       \
            }                                                                  \
            asm volatile("cp.async.commit_group;");                            \
            asm volatile("cp.async.wait_group 1;");                            \
        } else {                                                               \
            asm volatile("cp.async.wait_group 0;");                            \
        }                                                                      \
        __syncthreads();                                                       \
        unsigned Ast = Ab + st * 16384;                                        \
        unsigned Bst = Bb + st * 16384;                                        \
        _Pragma("unroll")                                                      \
        for (int kk = 0; kk < 4; kk++) {                                       \
            unsigned af[4][4];                                                 \
            _Pragma("unroll")                                                  \
            for (int mt = 0; mt < 4; mt++) {                                   \
                int r = wm * 64 + mt * 16 + (lane & 15);                       \
                int c = kk * 2 + (lane >> 4);                                  \
                LDSM4(af[mt][0], af[mt][1], af[mt][2], af[mt][3],              \
                      Ast + r * 128 + ((c ^ (r & 7)) << 4));                   \
            }                                                                  \
            _Pragma("unroll")                                                  \
            for (int nb = 0; nb < 2; nb++) {                                   \
                int r = wn * 32 + nb * 16 + (lane & 7) + ((lane >> 4) << 3);   \
                int c = kk * 2 + ((lane >> 3) & 1);                            \
                unsigned b0, b1, b2, b3;                                       \
                LDSM4(b0, b1, b2, b3, Bst + r * 128 + ((c ^ (r & 7)) << 4));   \
                _Pragma("unroll")                                              \
                for (int mt = 0; mt < 4; mt++) {                               \
                    mma16h(acc[mt][2*nb],   af[mt][0], af[mt][1], af[mt][2], af[mt][3], b0, b1); \
                    mma16h(acc[mt][2*nb+1], af[mt][0], af[mt][1], af[mt][2], af[mt][3], b2, b3); \
                }                                                              \
            }                                                                  \
        }                                                                      \
    }                                                                          \
    __VA_ARGS__

// ---------------- out-proj GEMM: fp32 C out ----------------
__global__ void __launch_bounds__(256, 2) gemm_h(
    const __half* __restrict__ A, const __half* __restrict__ B,
    float* __restrict__ C, int M, int N, int K)
{
    GEMM_BODY({
#pragma unroll
        for (int mt = 0; mt < 4; mt++)
#pragma unroll
            for (int nt = 0; nt < 4; nt++)
#pragma unroll
                for (int rp = 0; rp < 2; rp++) {
                    int gr = m0 + wm * 64 + mt * 16 + (lane >> 2) + rp * 8;
                    int gc = n0 + wn * 32 + nt * 8 + (lane & 3) * 2;
                    *(float2*)&C[(size_t)gr * N + gc] =
                        make_float2(acc[mt][nt][rp * 2], acc[mt][nt][rp * 2 + 1]);
                }
    })
}

// ---------------- QKV GEMM with fused RoPE epilogue (fp16 out) -------------
// N tile (128 cols) lies entirely within one of q/k/v (1024 each).
__global__ void __launch_bounds__(256, 2) gemm_qkv(
    const __half* __restrict__ A, const __half* __restrict__ B,
    const int* __restrict__ pos,
    __half* __restrict__ Qo, __half* __restrict__ Ko, __half* __restrict__ Vo,
    int M, int N, int K)
{
    GEMM_BODY({
        int part = n0 >> 10;                     // 0=q, 1=k, 2=v (uniform per CTA)
        __half* dst = (part == 0) ? Qo : (part == 1) ? Ko : Vo;
#pragma unroll
        for (int mt = 0; mt < 4; mt++)
#pragma unroll
            for (int rp = 0; rp < 2; rp++) {
                int gr = m0 + wm * 64 + mt * 16 + (lane >> 2) + rp * 8;   // s
                float p = (float)pos[gr];
#pragma unroll
                for (int nt = 0; nt < 4; nt++) {
                    int gc = n0 + wn * 32 + nt * 8 + (lane & 3) * 2;
                    int e = gc & 1023;
                    int hh = e >> 6;
                    int d = e & 63;
                    float v0 = acc[mt][nt][rp * 2];
                    float v1 = acc[mt][nt][rp * 2 + 1];
                    if (part < 2) {
                        int i = d >> 1;
                        float ang = p * exp2f(-(float)i * 0.41524101186092034f);
                        float sn;
                        float cs;
                        sincosf(ang, &sn, &cs);
                        float r0 = v0 * cs - v1 * sn;
                        float r1 = v0 * sn + v1 * cs;
                        if (part == 0) { r0 *= SC2; r1 *= SC2; }
                        v0 = r0;
                        v1 = r1;
                    }
                    *(__half2*)&dst[((size_t)hh * SEQ + gr) * DKH + d] =
                        __floats2half2_rn(v0, v1);
                }
            }
    })
}

// ---------------- Flash attention v4 (R12 proven): l-via-MMA + f16x2 ex2 ---
__global__ void __launch_bounds__(256, 2) flash4(
    const __half* __restrict__ Q, const __half* __restrict__ K,
    const __half* __restrict__ V, __half* __restrict__ Oout)
{
    extern __shared__ __half smh[];
    unsigned Qb = smem_u32(smh);
    unsigned Kb = Qb + 16384;
    unsigned Vb = Qb + 32768;

    int h = blockIdx.y;
    int qt = gridDim.x - 1 - blockIdx.x;
    int q0 = qt * 128;
    int tid = threadIdx.x;
    int w = tid >> 5, lane = tid & 31;

    const __half* Qg = Q + ((size_t)h * SEQ + q0) * DKH;
    const __half* Kg0 = K + (size_t)h * SEQ * DKH;
    const __half* Vg0 = V + (size_t)h * SEQ * DKH;

    int kt_end = (q0 + 127) >> 6;
    int wrmin = q0 + w * 16;
    int ktmax_w = (wrmin + 15) >> 6;

#pragma unroll
    for (int it = 0; it < 4; it++) {
        int f = tid + it * 256;
        int r = f >> 3, c = f & 7;
        cpa16(Qb + r * 128 + ((c ^ (r & 7)) << 4), Qg + r * DKH + c * 8);
    }
#pragma unroll
    for (int it = 0; it < 2; it++) {
        int f = tid + it * 256;
        int r = f >> 3, c = f & 7;
        unsigned soff = r * 128 + ((c ^ (r & 7)) << 4);
        cpa16(Kb + soff, Kg0 + r * DKH + c * 8);
        cpa16(Vb + soff, Vg0 + r * DKH + c * 8);
    }
    asm volatile("cp.async.commit_group;");

    unsigned qa[4][4];
    float o[8][4];
    float ol[4];
#pragma unroll
    for (int nt = 0; nt < 8; nt++)
#pragma unroll
        for (int c = 0; c < 4; c++) o[nt][c] = 0.0f;
#pragma unroll
    for (int c = 0; c < 4; c++) ol[c] = 0.0f;
    float mrow[2] = {-1e30f, -1e30f};

    for (int kt = 0; kt <= kt_end; kt++) {
        __syncthreads();
        int st = kt & 1;
        if (kt < kt_end) {
            const __half* Kg = Kg0 + (size_t)(kt + 1) * 64 * DKH;
            const __half* Vg = Vg0 + (size_t)(kt + 1) * 64 * DKH;
            unsigned sb2 = (st ^ 1) * 8192;
#pragma unroll
            for (int it = 0; it < 2; it++) {
                int f = tid + it * 256;
                int r = f >> 3, c = f & 7;
                unsigned soff = sb2 + r * 128 + ((c ^ (r & 7)) << 4);
                cpa16(Kb + soff, Kg + r * DKH + c * 8);
                cpa16(Vb + soff, Vg + r * DKH + c * 8);
            }
            asm volatile("cp.async.commit_group;");
            asm volatile("cp.async.wait_group 1;");
        } else {
            asm volatile("cp.async.wait_group 0;");
        }
        __syncthreads();

        if (kt == 0) {
            int r = w * 16 + (lane & 15);
            unsigned rowaddr = Qb + r * 128;
            int rx = r & 7;
#pragma unroll
            for (int kc = 0; kc < 4; kc++) {
                int cq = kc * 2 + (lane >> 4);
                LDSM4(qa[kc][0], qa[kc][1], qa[kc][2], qa[kc][3],
                      rowaddr + ((cq ^ rx) << 4));
            }
        }

        if (kt > ktmax_w) continue;

        unsigned Kst = Kb + st * 8192;
        unsigned Vst = Vb + st * 8192;

        float s[8][4];
#pragma unroll
        for (int nt = 0; nt < 8; nt++)
#pragma unroll
            for (int c = 0; c < 4; c++) s[nt][c] = 0.0f;

#pragma unroll
        for (int kc = 0; kc < 4; kc++) {
#pragma unroll
            for (int nb = 0; nb < 4; nb++) {
                int n = nb * 16 + (lane & 7) + ((lane >> 4) << 3);
                int ck = kc * 2 + ((lane >> 3) & 1);
                unsigned addr = Kst + n * 128 + ((ck ^ (n & 7)) << 4);
                unsigned b0, b1, b2, b3;
                LDSM4(b0, b1, b2, b3, addr);
                mma16h(s[2 * nb], qa[kc][0], qa[kc][1], qa[kc][2], qa[kc][3], b0, b1);
                mma16h(s[2 * nb + 1], qa[kc][0], qa[kc][1], qa[kc][2], qa[kc][3], b2, b3);
            }
        }

        bool need_mask = (kt * 64 + 63) > wrmin;
        float mnew[2] = {mrow[0], mrow[1]};
#pragma unroll
        for (int nt = 0; nt < 8; nt++)
#pragma unroll
            for (int c = 0; c < 4; c++) {
                float sv = s[nt][c];
                if (need_mask) {
                    int grow = wrmin + (lane >> 2) + ((c >= 2) ? 8 : 0);
                    int gcol = kt * 64 + nt * 8 + ((lane & 3) << 1) + (c & 1);
                    if (gcol > grow) sv = -1e30f;
                }
                s[nt][c] = sv;
                float& mm = mnew[c >> 1];
                mm = fmaxf(mm, sv);
            }
#pragma unroll
        for (int i = 0; i < 2; i++) {
            mnew[i] = fmaxf(mnew[i], __shfl_xor_sync(0xffffffffu, mnew[i], 1));
            mnew[i] = fmaxf(mnew[i], __shfl_xor_sync(0xffffffffu, mnew[i], 2));
        }
        float alpha0 = ex2f(mrow[0] - mnew[0]);
        float alpha1 = ex2f(mrow[1] - mnew[1]);
        mrow[0] = mnew[0]; mrow[1] = mnew[1];
#pragma unroll
        for (int nt = 0; nt < 8; nt++) {
            o[nt][0] *= alpha0; o[nt][1] *= alpha0;
            o[nt][2] *= alpha1; o[nt][3] *= alpha1;
        }
        ol[0] *= alpha0; ol[1] *= alpha0;
        ol[2] *= alpha1; ol[3] *= alpha1;

#pragma unroll
        for (int kc = 0; kc < 4; kc++) {
            unsigned a0 = h2ex2(pack_h2(s[2 * kc][0] - mnew[0], s[2 * kc][1] - mnew[0]));
            unsigned a1 = h2ex2(pack_h2(s[2 * kc][2] - mnew[1], s[2 * kc][3] - mnew[1]));
            unsigned a2 = h2ex2(pack_h2(s[2 * kc + 1][0] - mnew[0], s[2 * kc + 1][1] - mnew[0]));
            unsigned a3 = h2ex2(pack_h2(s[2 * kc + 1][2] - mnew[1], s[2 * kc + 1][3] - mnew[1]));
            mma16h(ol, a0, a1, a2, a3, ONESH2, ONESH2);
#pragma unroll
            for (int nb = 0; nb < 4; nb++) {
                int j = lane >> 3;
                int kr = kc * 16 + ((j & 1) << 3) + (lane & 7);
                int cv = nb * 2 + (j >> 1);
                unsigned addr = Vst + kr * 128 + ((cv ^ (kr & 7)) << 4);
                unsigned v0, v1, v2, v3;
                LDSM4T(v0, v1, v2, v3, addr);
                mma16h(o[2 * nb], a0, a1, a2, a3, v0, v1);
                mma16h(o[2 * nb + 1], a0, a1, a2, a3, v2, v3);
            }
        }
    }

    float inv0 = 1.0f / ol[0], inv1 = 1.0f / ol[2];
#pragma unroll
    for (int nt = 0; nt < 8; nt++)
#pragma unroll
        for (int rp = 0; rp < 2; rp++) {
            float invv = rp ? inv1 : inv0;
            int grow = wrmin + (lane >> 2) + 8 * rp;
            int gcol = h * DKH + nt * 8 + (lane & 3) * 2;
            *(__half2*)&Oout[(size_t)grow * DM + gcol] =
                __floats2half2_rn(o[nt][rp * 2] * invv, o[nt][rp * 2 + 1] * invv);
        }
}

// ---------------- launch ----------------
extern "C" void kernel_launch(void* const* d_in, const int* in_sizes, int n_in,
                              void* d_out, int out_size)
{
    const float* x    = (const float*)d_in[0];
    const float* Wqkv = (const float*)d_in[1];
    const float* Wo   = (const float*)d_in[2];
    const int*   pos  = (const int*)d_in[3];
    float* out = (float*)d_out;

    __half *xh, *wqkvh, *woh, *Q, *K, *V, *attnh;
    cudaGetSymbolAddress((void**)&xh,    g_xh);
    cudaGetSymbolAddress((void**)&wqkvh, g_wqkvh);
    cudaGetSymbolAddress((void**)&woh,   g_woh);
    cudaGetSymbolAddress((void**)&Q,     g_qh);
    cudaGetSymbolAddress((void**)&K,     g_kh);
    cudaGetSymbolAddress((void**)&V,     g_vh);
    cudaGetSymbolAddress((void**)&attnh, g_attnh);

    cudaFuncSetAttribute(flash4, cudaFuncAttributeMaxDynamicSharedMemorySize, 49152);

    f2h_all<<<(SEQ * DM + 4 * DM * DM) / 4 / 256, 256>>>(x, Wqkv, Wo, xh, wqkvh, woh);

    gemm_qkv<<<dim3(3 * DM / 128, SEQ / 128), 256>>>(xh, wqkvh, pos, Q, K, V,
                                                     SEQ, 3 * DM, DM);
    flash4<<<dim3(SEQ / 128, NH), 256, 49152>>>(Q, K, V, attnh);
    gemm_h<<<dim3(DM / 128, SEQ / 128), 256>>>(attnh, woh, out, SEQ, DM, DM);
}

// round 17
// speedup vs baseline: 1.2734x; 1.2734x over previous
#include <cuda_runtime.h>
#include <cuda_fp16.h>
#include <math.h>

#define SEQ 4096
#define DM 1024
#define NH 16
#define DKH 64
#define SC2 0.18033688011112042f   // 0.125 * log2(e)
#define ONESH2 0x3C003C00u         // half2(1.0, 1.0)

// ---------------- scratch ----------------
__device__ __half g_xh[SEQ * DM];
__device__ __half g_wqkvh[3 * DM * DM];
__device__ __half g_woh[DM * DM];
__device__ __half g_qh[NH * SEQ * DKH];
__device__ __half g_kh[NH * SEQ * DKH];
__device__ __half g_vh[NH * SEQ * DKH];
__device__ __half g_attnh[SEQ * DM];
__device__ float2 g_rope[SEQ * 32];    // (cos, sin) per (s, pair)

// ---------------- helpers ----------------
__device__ __forceinline__ float ex2f(float x) {
    float y;
    asm("ex2.approx.ftz.f32 %0, %1;" : "=f"(y) : "f"(x));
    return y;
}
__device__ __forceinline__ unsigned h2ex2(unsigned x) {
    unsigned y;
    asm("ex2.approx.f16x2 %0, %1;" : "=r"(y) : "r"(x));
    return y;
}
__device__ __forceinline__ void mma16h(float* d, unsigned a0, unsigned a1,
                                       unsigned a2, unsigned a3,
                                       unsigned b0, unsigned b1) {
    asm volatile(
        "mma.sync.aligned.m16n8k16.row.col.f32.f16.f16.f32 "
        "{%0,%1,%2,%3},{%4,%5,%6,%7},{%8,%9},{%0,%1,%2,%3};"
        : "+f"(d[0]), "+f"(d[1]), "+f"(d[2]), "+f"(d[3])
        : "r"(a0), "r"(a1), "r"(a2), "r"(a3), "r"(b0), "r"(b1));
}
__device__ __forceinline__ unsigned pack_h2(float x, float y) {
    __half2 h = __floats2half2_rn(x, y);
    return *(unsigned*)&h;
}
__device__ __forceinline__ unsigned smem_u32(const void* p) {
    unsigned a;
    asm("{ .reg .u64 t; cvta.to.shared.u64 t, %1; cvt.u32.u64 %0, t; }"
        : "=r"(a) : "l"(p));
    return a;
}
__device__ __forceinline__ void cpa16(unsigned s, const void* g) {
    asm volatile("cp.async.cg.shared.global [%0], [%1], 16;" :: "r"(s), "l"(g));
}
#define LDSM4(r0,r1,r2,r3,addr) \
    asm volatile("ldmatrix.sync.aligned.m8n8.x4.shared.b16 {%0,%1,%2,%3},[%4];" \
        : "=r"(r0),"=r"(r1),"=r"(r2),"=r"(r3) : "r"(addr))
#define LDSM4T(r0,r1,r2,r3,addr) \
    asm volatile("ldmatrix.sync.aligned.m8n8.x4.trans.shared.b16 {%0,%1,%2,%3},[%4];" \
        : "=r"(r0),"=r"(r1),"=r"(r2),"=r"(r3) : "r"(addr))

// ---------------- fused f32 -> f16 convert ----------------
__global__ void f2h_all(const float* __restrict__ x, const float* __restrict__ wqkv,
                        const float* __restrict__ wo, __half* __restrict__ xh,
                        __half* __restrict__ wqkvh, __half* __restrict__ woh)
{
    int i = blockIdx.x * blockDim.x + threadIdx.x;
    const int NX = SEQ * DM / 4;
    const int NW = 3 * DM * DM / 4;
    const float* src; __half* dst; int j;
    if (i < NX)            { src = x;    dst = xh;    j = i; }
    else if (i < NX + NW)  { src = wqkv; dst = wqkvh; j = i - NX; }
    else                   { src = wo;   dst = woh;   j = i - NX - NW; }
    float4 v = ((const float4*)src)[j];
    ((__half2*)dst)[2 * j]     = __floats2half2_rn(v.x, v.y);
    ((__half2*)dst)[2 * j + 1] = __floats2half2_rn(v.z, v.w);
}

// ---------------- RoPE cos/sin table ----------------
__global__ void rope_tab(const int* __restrict__ pos) {
    int idx = blockIdx.x * blockDim.x + threadIdx.x;   // < SEQ*32
    int s = idx >> 5, i = idx & 31;
    float p = (float)pos[s];
    float ang = p * exp2f(-(float)i * 0.41524101186092034f);
    float sn, cs;
    sincosf(ang, &sn, &cs);
    g_rope[idx] = make_float2(cs, sn);
}

// ======== shared GEMM mainloop (128x128, BK=64, double-buffered) ===========
#define GEMM_BODY(...)                                                         \
    __shared__ __half As[2][8192];                                             \
    __shared__ __half Bs[2][8192];                                             \
    unsigned Ab = smem_u32(As);                                                \
    unsigned Bb = smem_u32(Bs);                                                \
    int tid = threadIdx.x;                                                     \
    int lane = tid & 31, w = tid >> 5;                                         \
    int wm = w >> 2, wn = w & 3;                                               \
    int m0 = blockIdx.y * 128, n0 = blockIdx.x * 128;                          \
    float acc[4][4][4];                                                        \
    _Pragma("unroll")                                                          \
    for (int a = 0; a < 4; a++)                                                \
        _Pragma("unroll")                                                      \
        for (int b = 0; b < 4; b++)                                            \
            _Pragma("unroll")                                                  \
            for (int c = 0; c < 4; c++) acc[a][b][c] = 0.0f;                   \
    int nk = K / 64;                                                           \
    _Pragma("unroll")                                                          \
    for (int it = 0; it < 4; it++) {                                           \
        int f = tid + it * 256;                                                \
        int r = f >> 3, c = f & 7;                                             \
        unsigned soff = r * 128 + ((c ^ (r & 7)) << 4);                        \
        cpa16(Ab + soff, A + (size_t)(m0 + r) * K + c * 8);                    \
        cpa16(Bb + soff, B + (size_t)(n0 + r) * K + c * 8);                    \
    }                                                                          \
    asm volatile("cp.async.commit_group;");                                    \
    for (int kc = 0; kc < nk; kc++) {                                          \
        int st = kc & 1;                                                       \
        __syncthreads();                                                       \
        if (kc + 1 < nk) {                                                     \
            unsigned sb = (st ^ 1) * 16384;                                    \
            int kg = (kc + 1) * 64;                                            \
            _Pragma("unroll")                                                  \
            for (int it = 0; it < 4; it++) {                                   \
                int f = tid + it * 256;                                        \
                int r = f >> 3, c = f & 7;                                     \
                unsigned soff = sb + r * 128 + ((c ^ (r & 7)) << 4);           \
                cpa16(Ab + soff, A + (size_t)(m0 + r) * K + kg + c * 8);       \
                cpa16(Bb + soff, B + (size_t)(n0 + r) * K + kg + c * 8);       \
            }                                                                  \
            asm volatile("cp.async.commit_group;");                            \
            asm volatile("cp.async.wait_group 1;");                            \
        } else {                                                               \
            asm volatile("cp.async.wait_group 0;");                            \
        }                                                                      \
        __syncthreads();                                                       \
        unsigned Ast = Ab + st * 16384;                                        \
        unsigned Bst = Bb + st * 16384;                                        \
        _Pragma("unroll")                                                      \
        for (int kk = 0; kk < 4; kk++) {                                       \
            unsigned af[4][4];                                                 \
            _Pragma("unroll")                                                  \
            for (int mt = 0; mt < 4; mt++) {                                   \
                int r = wm * 64 + mt * 16 + (lane & 15);                       \
                int c = kk * 2 + (lane >> 4);                                  \
                LDSM4(af[mt][0], af[mt][1], af[mt][2], af[mt][3],              \
                      Ast + r * 128 + ((c ^ (r & 7)) << 4));                   \
            }                                                                  \
            _Pragma("unroll")                                                  \
            for (int nb = 0; nb < 2; nb++) {                                   \
                int r = wn * 32 + nb * 16 + (lane & 7) + ((lane >> 4) << 3);   \
                int c = kk * 2 + ((lane >> 3) & 1);                            \
                unsigned b0, b1, b2, b3;                                       \
                LDSM4(b0, b1, b2, b3, Bst + r * 128 + ((c ^ (r & 7)) << 4));   \
                _Pragma("unroll")                                              \
                for (int mt = 0; mt < 4; mt++) {                               \
                    mma16h(acc[mt][2*nb],   af[mt][0], af[mt][1], af[mt][2], af[mt][3], b0, b1); \
                    mma16h(acc[mt][2*nb+1], af[mt][0], af[mt][1], af[mt][2], af[mt][3], b2, b3); \
                }                                                              \
            }                                                                  \
        }                                                                      \
    }                                                                          \
    __VA_ARGS__

// ---------------- out-proj GEMM: fp32 C out ----------------
__global__ void __launch_bounds__(256, 2) gemm_h(
    const __half* __restrict__ A, const __half* __restrict__ B,
    float* __restrict__ C, int M, int N, int K)
{
    GEMM_BODY({
#pragma unroll
        for (int mt = 0; mt < 4; mt++)
#pragma unroll
            for (int nt = 0; nt < 4; nt++)
#pragma unroll
                for (int rp = 0; rp < 2; rp++) {
                    int gr = m0 + wm * 64 + mt * 16 + (lane >> 2) + rp * 8;
                    int gc = n0 + wn * 32 + nt * 8 + (lane & 3) * 2;
                    *(float2*)&C[(size_t)gr * N + gc] =
                        make_float2(acc[mt][nt][rp * 2], acc[mt][nt][rp * 2 + 1]);
                }
    })
}

// ---------------- QKV GEMM + RoPE epilogue via table (fp16 out) ------------
__global__ void __launch_bounds__(256, 2) gemm_qkv(
    const __half* __restrict__ A, const __half* __restrict__ B,
    __half* __restrict__ Qo, __half* __restrict__ Ko, __half* __restrict__ Vo,
    int M, int N, int K)
{
    GEMM_BODY({
        int part = n0 >> 10;                     // 0=q, 1=k, 2=v (uniform per CTA)
        __half* dst = (part == 0) ? Qo : (part == 1) ? Ko : Vo;
#pragma unroll
        for (int mt = 0; mt < 4; mt++)
#pragma unroll
            for (int rp = 0; rp < 2; rp++) {
                int gr = m0 + wm * 64 + mt * 16 + (lane >> 2) + rp * 8;   // s
#pragma unroll
                for (int nt = 0; nt < 4; nt++) {
                    int gc = n0 + wn * 32 + nt * 8 + (lane & 3) * 2;
                    int e = gc & 1023;
                    int hh = e >> 6;
                    int d = e & 63;
                    float v0 = acc[mt][nt][rp * 2];
                    float v1 = acc[mt][nt][rp * 2 + 1];
                    if (part < 2) {
                        float2 cssn = g_rope[gr * 32 + (d >> 1)];
                        float r0 = v0 * cssn.x - v1 * cssn.y;
                        float r1 = v0 * cssn.y + v1 * cssn.x;
                        if (part == 0) { r0 *= SC2; r1 *= SC2; }
                        v0 = r0;
                        v1 = r1;
                    }
                    *(__half2*)&dst[((size_t)hh * SEQ + gr) * DKH + d] =
                        __floats2half2_rn(v0, v1);
                }
            }
    })
}

// ---------------- Flash attention v4 (R12 proven): l-via-MMA + f16x2 ex2 ---
__global__ void __launch_bounds__(256, 2) flash4(
    const __half* __restrict__ Q, const __half* __restrict__ K,
    const __half* __restrict__ V, __half* __restrict__ Oout)
{
    extern __shared__ __half smh[];
    unsigned Qb = smem_u32(smh);
    unsigned Kb = Qb + 16384;
    unsigned Vb = Qb + 32768;

    int h = blockIdx.y;
    int qt = gridDim.x - 1 - blockIdx.x;
    int q0 = qt * 128;
    int tid = threadIdx.x;
    int w = tid >> 5, lane = tid & 31;

    const __half* Qg = Q + ((size_t)h * SEQ + q0) * DKH;
    const __half* Kg0 = K + (size_t)h * SEQ * DKH;
    const __half* Vg0 = V + (size_t)h * SEQ * DKH;

    int kt_end = (q0 + 127) >> 6;
    int wrmin = q0 + w * 16;
    int ktmax_w = (wrmin + 15) >> 6;

#pragma unroll
    for (int it = 0; it < 4; it++) {
        int f = tid + it * 256;
        int r = f >> 3, c = f & 7;
        cpa16(Qb + r * 128 + ((c ^ (r & 7)) << 4), Qg + r * DKH + c * 8);
    }
#pragma unroll
    for (int it = 0; it < 2; it++) {
        int f = tid + it * 256;
        int r = f >> 3, c = f & 7;
        unsigned soff = r * 128 + ((c ^ (r & 7)) << 4);
        cpa16(Kb + soff, Kg0 + r * DKH + c * 8);
        cpa16(Vb + soff, Vg0 + r * DKH + c * 8);
    }
    asm volatile("cp.async.commit_group;");

    unsigned qa[4][4];
    float o[8][4];
    float ol[4];
#pragma unroll
    for (int nt = 0; nt < 8; nt++)
#pragma unroll
        for (int c = 0; c < 4; c++) o[nt][c] = 0.0f;
#pragma unroll
    for (int c = 0; c < 4; c++) ol[c] = 0.0f;
    float mrow[2] = {-1e30f, -1e30f};

    for (int kt = 0; kt <= kt_end; kt++) {
        __syncthreads();
        int st = kt & 1;
        if (kt < kt_end) {
            const __half* Kg = Kg0 + (size_t)(kt + 1) * 64 * DKH;
            const __half* Vg = Vg0 + (size_t)(kt + 1) * 64 * DKH;
            unsigned sb2 = (st ^ 1) * 8192;
#pragma unroll
            for (int it = 0; it < 2; it++) {
                int f = tid + it * 256;
                int r = f >> 3, c = f & 7;
                unsigned soff = sb2 + r * 128 + ((c ^ (r & 7)) << 4);
                cpa16(Kb + soff, Kg + r * DKH + c * 8);
                cpa16(Vb + soff, Vg + r * DKH + c * 8);
            }
            asm volatile("cp.async.commit_group;");
            asm volatile("cp.async.wait_group 1;");
        } else {
            asm volatile("cp.async.wait_group 0;");
        }
        __syncthreads();

        if (kt == 0) {
            int r = w * 16 + (lane & 15);
            unsigned rowaddr = Qb + r * 128;
            int rx = r & 7;
#pragma unroll
            for (int kc = 0; kc < 4; kc++) {
                int cq = kc * 2 + (lane >> 4);
                LDSM4(qa[kc][0], qa[kc][1], qa[kc][2], qa[kc][3],
                      rowaddr + ((cq ^ rx) << 4));
            }
        }

        if (kt > ktmax_w) continue;

        unsigned Kst = Kb + st * 8192;
        unsigned Vst = Vb + st * 8192;

        float s[8][4];
#pragma unroll
        for (int nt = 0; nt < 8; nt++)
#pragma unroll
            for (int c = 0; c < 4; c++) s[nt][c] = 0.0f;

#pragma unroll
        for (int kc = 0; kc < 4; kc++) {
#pragma unroll
            for (int nb = 0; nb < 4; nb++) {
                int n = nb * 16 + (lane & 7) + ((lane >> 4) << 3);
                int ck = kc * 2 + ((lane >> 3) & 1);
                unsigned addr = Kst + n * 128 + ((ck ^ (n & 7)) << 4);
                unsigned b0, b1, b2, b3;
                LDSM4(b0, b1, b2, b3, addr);
                mma16h(s[2 * nb], qa[kc][0], qa[kc][1], qa[kc][2], qa[kc][3], b0, b1);
                mma16h(s[2 * nb + 1], qa[kc][0], qa[kc][1], qa[kc][2], qa[kc][3], b2, b3);
            }
        }

        bool need_mask = (kt * 64 + 63) > wrmin;
        float mnew[2] = {mrow[0], mrow[1]};
#pragma unroll
        for (int nt = 0; nt < 8; nt++)
#pragma unroll
            for (int c = 0; c < 4; c++) {
                float sv = s[nt][c];
                if (need_mask) {
                    int grow = wrmin + (lane >> 2) + ((c >= 2) ? 8 : 0);
                    int gcol = kt * 64 + nt * 8 + ((lane & 3) << 1) + (c & 1);
                    if (gcol > grow) sv = -1e30f;
                }
                s[nt][c] = sv;
                float& mm = mnew[c >> 1];
                mm = fmaxf(mm, sv);
            }
#pragma unroll
        for (int i = 0; i < 2; i++) {
            mnew[i] = fmaxf(mnew[i], __shfl_xor_sync(0xffffffffu, mnew[i], 1));
            mnew[i] = fmaxf(mnew[i], __shfl_xor_sync(0xffffffffu, mnew[i], 2));
        }
        float alpha0 = ex2f(mrow[0] - mnew[0]);
        float alpha1 = ex2f(mrow[1] - mnew[1]);
        mrow[0] = mnew[0]; mrow[1] = mnew[1];
#pragma unroll
        for (int nt = 0; nt < 8; nt++) {
            o[nt][0] *= alpha0; o[nt][1] *= alpha0;
            o[nt][2] *= alpha1; o[nt][3] *= alpha1;
        }
        ol[0] *= alpha0; ol[1] *= alpha0;
        ol[2] *= alpha1; ol[3] *= alpha1;

#pragma unroll
        for (int kc = 0; kc < 4; kc++) {
            unsigned a0 = h2ex2(pack_h2(s[2 * kc][0] - mnew[0], s[2 * kc][1] - mnew[0]));
            unsigned a1 = h2ex2(pack_h2(s[2 * kc][2] - mnew[1], s[2 * kc][3] - mnew[1]));
            unsigned a2 = h2ex2(pack_h2(s[2 * kc + 1][0] - mnew[0], s[2 * kc + 1][1] - mnew[0]));
            unsigned a3 = h2ex2(pack_h2(s[2 * kc + 1][2] - mnew[1], s[2 * kc + 1][3] - mnew[1]));
            mma16h(ol, a0, a1, a2, a3, ONESH2, ONESH2);
#pragma unroll
            for (int nb = 0; nb < 4; nb++) {
                int j = lane >> 3;
                int kr = kc * 16 + ((j & 1) << 3) + (lane & 7);
                int cv = nb * 2 + (j >> 1);
                unsigned addr = Vst + kr * 128 + ((cv ^ (kr & 7)) << 4);
                unsigned v0, v1, v2, v3;
                LDSM4T(v0, v1, v2, v3, addr);
                mma16h(o[2 * nb], a0, a1, a2, a3, v0, v1);
                mma16h(o[2 * nb + 1], a0, a1, a2, a3, v2, v3);
            }
        }
    }

    float inv0 = 1.0f / ol[0], inv1 = 1.0f / ol[2];
#pragma unroll
    for (int nt = 0; nt < 8; nt++)
#pragma unroll
        for (int rp = 0; rp < 2; rp++) {
            float invv = rp ? inv1 : inv0;
            int grow = wrmin + (lane >> 2) + 8 * rp;
            int gcol = h * DKH + nt * 8 + (lane & 3) * 2;
            *(__half2*)&Oout[(size_t)grow * DM + gcol] =
                __floats2half2_rn(o[nt][rp * 2] * invv, o[nt][rp * 2 + 1] * invv);
        }
}

// ---------------- launch ----------------
extern "C" void kernel_launch(void* const* d_in, const int* in_sizes, int n_in,
                              void* d_out, int out_size)
{
    const float* x    = (const float*)d_in[0];
    const float* Wqkv = (const float*)d_in[1];
    const float* Wo   = (const float*)d_in[2];
    const int*   pos  = (const int*)d_in[3];
    float* out = (float*)d_out;

    __half *xh, *wqkvh, *woh, *Q, *K, *V, *attnh;
    cudaGetSymbolAddress((void**)&xh,    g_xh);
    cudaGetSymbolAddress((void**)&wqkvh, g_wqkvh);
    cudaGetSymbolAddress((void**)&woh,   g_woh);
    cudaGetSymbolAddress((void**)&Q,     g_qh);
    cudaGetSymbolAddress((void**)&K,     g_kh);
    cudaGetSymbolAddress((void**)&V,     g_vh);
    cudaGetSymbolAddress((void**)&attnh, g_attnh);

    cudaFuncSetAttribute(flash4, cudaFuncAttributeMaxDynamicSharedMemorySize, 49152);

    f2h_all<<<(SEQ * DM + 4 * DM * DM) / 4 / 256, 256>>>(x, Wqkv, Wo, xh, wqkvh, woh);
    rope_tab<<<SEQ * 32 / 256, 256>>>(pos);

    gemm_qkv<<<dim3(3 * DM / 128, SEQ / 128), 256>>>(xh, wqkvh, Q, K, V,
                                                     SEQ, 3 * DM, DM);
    flash4<<<dim3(SEQ / 128, NH), 256, 49152>>>(Q, K, V, attnh);
    gemm_h<<<dim3(DM / 128, SEQ / 128), 256>>>(attnh, woh, out, SEQ, DM, DM);
}